// round 1
// baseline (speedup 1.0000x reference)
#include <cuda_runtime.h>
#include <cstdint>

#define QT  1024
#define KVT 4096
#define HD  128
#define BM  128
#define BN  128
#define BK  16

__device__ __forceinline__ unsigned long long pack2(float lo, float hi) {
    unsigned long long r;
    asm("mov.b64 %0, {%1, %2};" : "=l"(r) : "f"(lo), "f"(hi));
    return r;
}
__device__ __forceinline__ void unpack2(unsigned long long v, float& lo, float& hi) {
    asm("mov.b64 {%0, %1}, %2;" : "=f"(lo), "=f"(hi) : "l"(v));
}
__device__ __forceinline__ unsigned long long ffma2(unsigned long long a,
                                                    unsigned long long b,
                                                    unsigned long long c) {
    unsigned long long d;
    asm("fma.rn.f32x2 %0, %1, %2, %3;" : "=l"(d) : "l"(a), "l"(b), "l"(c));
    return d;
}

// C[1024,4096] = A[1024,128] * B[4096,128]^T, per batch (32 batches).
// Tile 128x128, 256 threads, each thread 8x8 outputs, inner product via
// packed f32x2 FMA (2 FMAs per instruction on the fma pipe).
__global__ __launch_bounds__(256, 2)
void qkbmm_kernel(const float* __restrict__ Q,
                  const float* __restrict__ K,
                  float* __restrict__ O) {
    const int batch = blockIdx.z;        // 0..31  (B*M)
    const int mt    = blockIdx.y;        // 0..7   (QT/128)
    const int nt    = blockIdx.x;        // 0..31  (KVT/128)

    const float* A = Q + (size_t)batch * QT  * HD + (size_t)mt * BM * HD;
    const float* B = K + (size_t)batch * KVT * HD + (size_t)nt * BN * HD;
    float*       C = O + (size_t)batch * QT * KVT + (size_t)mt * BM * KVT
                       + (size_t)nt * BN;

    __shared__ float As[BK][BM];
    __shared__ float Bs[BK][BN];

    const int tid = threadIdx.x;
    const int tx  = tid & 15;   // 0..15 -> N
    const int ty  = tid >> 4;   // 0..15 -> M

    unsigned long long acc[8][4];
    #pragma unroll
    for (int i = 0; i < 8; i++)
        #pragma unroll
        for (int j = 0; j < 4; j++)
            acc[i][j] = pack2(0.f, 0.f);

    // Global->shared load mapping: 128 rows x 16 cols per tile per matrix,
    // 512 float4 / 256 threads = 2 float4 each per matrix.
    const int lrow = tid >> 2;         // 0..63
    const int lcol = (tid & 3) * 4;    // 0,4,8,12

    for (int ko = 0; ko < HD; ko += BK) {
        #pragma unroll
        for (int h = 0; h < 2; h++) {
            const int r = lrow + h * 64;
            float4 va = *reinterpret_cast<const float4*>(A + (size_t)r * HD + ko + lcol);
            As[lcol + 0][r] = va.x;
            As[lcol + 1][r] = va.y;
            As[lcol + 2][r] = va.z;
            As[lcol + 3][r] = va.w;
            float4 vb = *reinterpret_cast<const float4*>(B + (size_t)r * HD + ko + lcol);
            Bs[lcol + 0][r] = vb.x;
            Bs[lcol + 1][r] = vb.y;
            Bs[lcol + 2][r] = vb.z;
            Bs[lcol + 3][r] = vb.w;
        }
        __syncthreads();

        #pragma unroll
        for (int kk = 0; kk < BK; kk++) {
            float4 a0 = *reinterpret_cast<const float4*>(&As[kk][ty * 8]);
            float4 a1 = *reinterpret_cast<const float4*>(&As[kk][ty * 8 + 4]);
            float4 b0 = *reinterpret_cast<const float4*>(&Bs[kk][tx * 8]);
            float4 b1 = *reinterpret_cast<const float4*>(&Bs[kk][tx * 8 + 4]);

            unsigned long long bp[4];
            bp[0] = pack2(b0.x, b0.y);
            bp[1] = pack2(b0.z, b0.w);
            bp[2] = pack2(b1.x, b1.y);
            bp[3] = pack2(b1.z, b1.w);

            const float av[8] = {a0.x, a0.y, a0.z, a0.w, a1.x, a1.y, a1.z, a1.w};
            #pragma unroll
            for (int i = 0; i < 8; i++) {
                const unsigned long long ap = pack2(av[i], av[i]);
                #pragma unroll
                for (int j = 0; j < 4; j++)
                    acc[i][j] = ffma2(ap, bp[j], acc[i][j]);
            }
        }
        __syncthreads();
    }

    // Epilogue: 8 rows x 8 cols per thread, two float4 stores per row.
    #pragma unroll
    for (int i = 0; i < 8; i++) {
        float v[8];
        #pragma unroll
        for (int j = 0; j < 4; j++)
            unpack2(acc[i][j], v[2 * j], v[2 * j + 1]);
        float4* dst = reinterpret_cast<float4*>(C + (size_t)(ty * 8 + i) * KVT + tx * 8);
        dst[0] = make_float4(v[0], v[1], v[2], v[3]);
        dst[1] = make_float4(v[4], v[5], v[6], v[7]);
    }
}

extern "C" void kernel_launch(void* const* d_in, const int* in_sizes, int n_in,
                              void* d_out, int out_size) {
    const float* q = (const float*)d_in[0];   // [2,16,1024,128]
    const float* k = (const float*)d_in[1];   // [2,16,4096,128]
    float* out = (float*)d_out;               // [2,16,1024,4096]
    dim3 grid(KVT / BN, QT / BM, 32);
    qkbmm_kernel<<<grid, 256>>>(q, k, out);
}

// round 8
// speedup vs baseline: 2.6927x; 2.6927x over previous
#include <cuda_runtime.h>
#include <cuda_bf16.h>
#include <cstdint>

#define QT    1024
#define KVT   4096
#define HD    128
#define KC    32      // K chunk
#define PITCH 40      // bf16 elements per smem row (80 bytes)

__device__ __forceinline__ uint32_t smem_u32(const void* p) {
    uint32_t a;
    asm("{ .reg .u64 t; cvta.to.shared.u64 t, %1; cvt.u32.u64 %0, t; }" : "=r"(a) : "l"(p));
    return a;
}

__device__ __forceinline__ void ldmx4(uint32_t* r, uint32_t addr) {
    asm volatile("ldmatrix.sync.aligned.m8n8.x4.shared.b16 {%0,%1,%2,%3}, [%4];"
                 : "=r"(r[0]), "=r"(r[1]), "=r"(r[2]), "=r"(r[3]) : "r"(addr));
}

__device__ __forceinline__ void mma_bf16(float* c, const uint32_t* a,
                                         uint32_t b0, uint32_t b1) {
    asm volatile(
        "mma.sync.aligned.m16n8k16.row.col.f32.bf16.bf16.f32 "
        "{%0,%1,%2,%3}, {%4,%5,%6,%7}, {%8,%9}, {%0,%1,%2,%3};"
        : "+f"(c[0]), "+f"(c[1]), "+f"(c[2]), "+f"(c[3])
        : "r"(a[0]), "r"(a[1]), "r"(a[2]), "r"(a[3]), "r"(b0), "r"(b1));
}

// split one float4 into packed bf16x2 hi and lo words
__device__ __forceinline__ void split4(float4 v, uint32_t& h01, uint32_t& h23,
                                       uint32_t& l01, uint32_t& l23) {
    __nv_bfloat16 hx = __float2bfloat16(v.x), hy = __float2bfloat16(v.y);
    __nv_bfloat16 hz = __float2bfloat16(v.z), hw = __float2bfloat16(v.w);
    __nv_bfloat162 h0 = __nv_bfloat162(hx, hy), h1 = __nv_bfloat162(hz, hw);
    h01 = *reinterpret_cast<uint32_t*>(&h0);
    h23 = *reinterpret_cast<uint32_t*>(&h1);
    __nv_bfloat16 lx = __float2bfloat16(v.x - __bfloat162float(hx));
    __nv_bfloat16 ly = __float2bfloat16(v.y - __bfloat162float(hy));
    __nv_bfloat16 lz = __float2bfloat16(v.z - __bfloat162float(hz));
    __nv_bfloat16 lw = __float2bfloat16(v.w - __bfloat162float(hw));
    __nv_bfloat162 l0 = __nv_bfloat162(lx, ly), l1 = __nv_bfloat162(lz, lw);
    l01 = *reinterpret_cast<uint32_t*>(&l0);
    l23 = *reinterpret_cast<uint32_t*>(&l1);
}

__global__ void __launch_bounds__(256, 2)
qk_mma_kernel(const float* __restrict__ Q, const float* __restrict__ K,
              float* __restrict__ O) {
    __shared__ __align__(16) __nv_bfloat16 sAhi[128 * PITCH];
    __shared__ __align__(16) __nv_bfloat16 sAlo[128 * PITCH];
    __shared__ __align__(16) __nv_bfloat16 sBhi[128 * PITCH];
    __shared__ __align__(16) __nv_bfloat16 sBlo[128 * PITCH];

    const int tid  = threadIdx.x;
    const int wid  = tid >> 5;
    const int lane = tid & 31;

    const int cta   = blockIdx.x;
    const int nt_   = cta & 31;          // KVT/128
    const int mt_   = (cta >> 5) & 7;    // QT/128
    const int batch = cta >> 8;          // 32 batches
    const float* A = Q + ((size_t)batch * QT  + (size_t)mt_ * 128) * HD;
    const float* B = K + ((size_t)batch * KVT + (size_t)nt_ * 128) * HD;
    float*       C = O + (size_t)batch * QT * KVT + (size_t)mt_ * 128 * KVT
                       + (size_t)nt_ * 128;

    const int m_base = (wid & 1) * 64;   // warp M offset
    const int n_base = (wid >> 1) * 32;  // warp N offset

    float c[4][4][4];                    // [m-tile][n-tile][reg]
    #pragma unroll
    for (int i = 0; i < 4; i++)
        #pragma unroll
        for (int j = 0; j < 4; j++)
            #pragma unroll
            for (int r = 0; r < 4; r++) c[i][j][r] = 0.f;

    const uint32_t uAhi = smem_u32(sAhi), uAlo = smem_u32(sAlo);
    const uint32_t uBhi = smem_u32(sBhi), uBlo = smem_u32(sBlo);

    // ldmatrix per-lane address components
    const int a_row = lane & 15;                            // 0..15
    const int a_col = (lane & 16) ? 8 : 0;                  // +8 cols for mats 2,3
    const int b_row = (lane & 7) + ((lane & 16) ? 8 : 0);   // n offset
    const int b_col = (lane & 8) ? 8 : 0;                   // +8 k for mats 1,3

    for (int ch = 0; ch < HD / KC; ch++) {
        __syncthreads();   // previous chunk's compute done before overwrite
        // ---- load chunk [128 rows x 32 cols] of A and B, split hi/lo ----
        #pragma unroll
        for (int j = 0; j < 4; j++) {
            const int f    = tid + 256 * j;     // 0..1023
            const int row  = f >> 3;            // 0..127
            const int colg = (f & 7) * 4;       // 0..28
            const int soff = row * PITCH + colg;
            uint32_t h01, h23, l01, l23;

            float4 va = *reinterpret_cast<const float4*>(
                A + (size_t)row * HD + ch * KC + colg);
            split4(va, h01, h23, l01, l23);
            *reinterpret_cast<uint32_t*>(&sAhi[soff])     = h01;
            *reinterpret_cast<uint32_t*>(&sAhi[soff + 2]) = h23;
            *reinterpret_cast<uint32_t*>(&sAlo[soff])     = l01;
            *reinterpret_cast<uint32_t*>(&sAlo[soff + 2]) = l23;

            float4 vb = *reinterpret_cast<const float4*>(
                B + (size_t)row * HD + ch * KC + colg);
            split4(vb, h01, h23, l01, l23);
            *reinterpret_cast<uint32_t*>(&sBhi[soff])     = h01;
            *reinterpret_cast<uint32_t*>(&sBhi[soff + 2]) = h23;
            *reinterpret_cast<uint32_t*>(&sBlo[soff])     = l01;
            *reinterpret_cast<uint32_t*>(&sBlo[soff + 2]) = l23;
        }
        __syncthreads();

        // ---- compute: 2 k16 steps per chunk ----
        #pragma unroll
        for (int ks = 0; ks < 2; ks++) {
            const int k0 = ks * 16;
            uint32_t ah[4][4], al[4][4], bh[2][4], bl[2][4];
            #pragma unroll
            for (int mt = 0; mt < 4; mt++) {
                const uint32_t off =
                    ((uint32_t)(m_base + mt * 16 + a_row) * PITCH
                     + (uint32_t)(k0 + a_col)) * 2u;
                ldmx4(ah[mt], uAhi + off);
                ldmx4(al[mt], uAlo + off);
            }
            #pragma unroll
            for (int bt = 0; bt < 2; bt++) {
                const uint32_t off =
                    ((uint32_t)(n_base + bt * 16 + b_row) * PITCH
                     + (uint32_t)(k0 + b_col)) * 2u;
                ldmx4(bh[bt], uBhi + off);
                ldmx4(bl[bt], uBlo + off);
            }
            // pass 1: Ahi * Bhi
            #pragma unroll
            for (int mt = 0; mt < 4; mt++)
                #pragma unroll
                for (int nt = 0; nt < 4; nt++)
                    mma_bf16(c[mt][nt], ah[mt],
                             bh[nt >> 1][(nt & 1) * 2], bh[nt >> 1][(nt & 1) * 2 + 1]);
            // pass 2: Ahi * Blo
            #pragma unroll
            for (int mt = 0; mt < 4; mt++)
                #pragma unroll
                for (int nt = 0; nt < 4; nt++)
                    mma_bf16(c[mt][nt], ah[mt],
                             bl[nt >> 1][(nt & 1) * 2], bl[nt >> 1][(nt & 1) * 2 + 1]);
            // pass 3: Alo * Bhi
            #pragma unroll
            for (int mt = 0; mt < 4; mt++)
                #pragma unroll
                for (int nt = 0; nt < 4; nt++)
                    mma_bf16(c[mt][nt], al[mt],
                             bh[nt >> 1][(nt & 1) * 2], bh[nt >> 1][(nt & 1) * 2 + 1]);
        }
    }

    // ---- epilogue: direct STG.64, full 32B sectors ----
    const int er = lane >> 2;          // 0..7
    const int ec = (lane & 3) * 2;     // 0,2,4,6
    #pragma unroll
    for (int mt = 0; mt < 4; mt++) {
        #pragma unroll
        for (int nt = 0; nt < 4; nt++) {
            const int row = m_base + mt * 16 + er;
            const int col = n_base + nt * 8 + ec;
            *reinterpret_cast<float2*>(C + (size_t)row * KVT + col) =
                make_float2(c[mt][nt][0], c[mt][nt][1]);
            *reinterpret_cast<float2*>(C + (size_t)(row + 8) * KVT + col) =
                make_float2(c[mt][nt][2], c[mt][nt][3]);
        }
    }
}

extern "C" void kernel_launch(void* const* d_in, const int* in_sizes, int n_in,
                              void* d_out, int out_size) {
    const float* q = (const float*)d_in[0];   // [2,16,1024,128]
    const float* k = (const float*)d_in[1];   // [2,16,4096,128]
    float* out = (float*)d_out;               // [2,16,1024,4096]
    qk_mma_kernel<<<8192, 256>>>(q, k, out);
}

// round 13
// speedup vs baseline: 4.0719x; 1.5122x over previous
#include <cuda_runtime.h>
#include <cuda_fp16.h>
#include <cstdint>

#define QT    1024
#define KVT   4096
#define HD    128
#define KC    32      // K chunk
#define PITCH 40      // fp16 elements per smem row (80 bytes)

__device__ __forceinline__ uint32_t smem_u32(const void* p) {
    uint32_t a;
    asm("{ .reg .u64 t; cvta.to.shared.u64 t, %1; cvt.u32.u64 %0, t; }" : "=r"(a) : "l"(p));
    return a;
}

__device__ __forceinline__ void ldmx4(uint32_t* r, uint32_t addr) {
    asm volatile("ldmatrix.sync.aligned.m8n8.x4.shared.b16 {%0,%1,%2,%3}, [%4];"
                 : "=r"(r[0]), "=r"(r[1]), "=r"(r[2]), "=r"(r[3]) : "r"(addr));
}

__device__ __forceinline__ void mma_f16(float* c, const uint32_t* a,
                                        uint32_t b0, uint32_t b1) {
    asm volatile(
        "mma.sync.aligned.m16n8k16.row.col.f32.f16.f16.f32 "
        "{%0,%1,%2,%3}, {%4,%5,%6,%7}, {%8,%9}, {%0,%1,%2,%3};"
        : "+f"(c[0]), "+f"(c[1]), "+f"(c[2]), "+f"(c[3])
        : "r"(a[0]), "r"(a[1]), "r"(a[2]), "r"(a[3]), "r"(b0), "r"(b1));
}

__global__ void __launch_bounds__(256, 2)
qk_f16_kernel(const float* __restrict__ Q, const float* __restrict__ K,
              float* __restrict__ O) {
    __shared__ __align__(16) __half sA[128 * PITCH];
    __shared__ __align__(16) __half sB[128 * PITCH];

    const int tid  = threadIdx.x;
    const int wid  = tid >> 5;
    const int lane = tid & 31;

    const int cta   = blockIdx.x;
    const int nt_   = cta & 31;          // KVT/128
    const int mt_   = (cta >> 5) & 7;    // QT/128
    const int batch = cta >> 8;          // 32 batches
    const float* A = Q + ((size_t)batch * QT  + (size_t)mt_ * 128) * HD;
    const float* B = K + ((size_t)batch * KVT + (size_t)nt_ * 128) * HD;
    float*       C = O + (size_t)batch * QT * KVT + (size_t)mt_ * 128 * KVT
                       + (size_t)nt_ * 128;

    const int m_base = (wid & 1) * 64;   // warp M offset
    const int n_base = (wid >> 1) * 32;  // warp N offset

    float c[4][4][4];                    // [m-tile][n-tile][reg]
    #pragma unroll
    for (int i = 0; i < 4; i++)
        #pragma unroll
        for (int j = 0; j < 4; j++)
            #pragma unroll
            for (int r = 0; r < 4; r++) c[i][j][r] = 0.f;

    const uint32_t uA = smem_u32(sA), uB = smem_u32(sB);

    // ldmatrix per-lane address components (identical to validated bf16 kernel)
    const int a_row = lane & 15;
    const int a_col = (lane & 16) ? 8 : 0;
    const int b_row = (lane & 7) + ((lane & 16) ? 8 : 0);
    const int b_col = (lane & 8) ? 8 : 0;

    float4 aR[4], bR[4];

    // ---- prologue: LDG chunk 0 ----
    #pragma unroll
    for (int j = 0; j < 4; j++) {
        const int f   = tid + 256 * j;
        const int row = f >> 3;
        const int cg  = (f & 7) * 4;
        aR[j] = *reinterpret_cast<const float4*>(A + (size_t)row * HD + cg);
        bR[j] = *reinterpret_cast<const float4*>(B + (size_t)row * HD + cg);
    }

    #pragma unroll
    for (int ch = 0; ch < 4; ch++) {
        __syncthreads();   // previous chunk's compute done: smem free
        // ---- cvt + STS.64 current chunk from regs ----
        #pragma unroll
        for (int j = 0; j < 4; j++) {
            const int f    = tid + 256 * j;
            const int row  = f >> 3;
            const int cg   = (f & 7) * 4;
            const int soff = row * PITCH + cg;
            {
                __half2 h0 = __floats2half2_rn(aR[j].x, aR[j].y);
                __half2 h1 = __floats2half2_rn(aR[j].z, aR[j].w);
                uint2 u;
                u.x = *reinterpret_cast<uint32_t*>(&h0);
                u.y = *reinterpret_cast<uint32_t*>(&h1);
                *reinterpret_cast<uint2*>(&sA[soff]) = u;
            }
            {
                __half2 h0 = __floats2half2_rn(bR[j].x, bR[j].y);
                __half2 h1 = __floats2half2_rn(bR[j].z, bR[j].w);
                uint2 u;
                u.x = *reinterpret_cast<uint32_t*>(&h0);
                u.y = *reinterpret_cast<uint32_t*>(&h1);
                *reinterpret_cast<uint2*>(&sB[soff]) = u;
            }
        }
        __syncthreads();

        // ---- prefetch next chunk's LDG (latency hides behind compute) ----
        if (ch < 3) {
            #pragma unroll
            for (int j = 0; j < 4; j++) {
                const int f   = tid + 256 * j;
                const int row = f >> 3;
                const int cg  = (f & 7) * 4 + (ch + 1) * KC;
                aR[j] = *reinterpret_cast<const float4*>(A + (size_t)row * HD + cg);
                bR[j] = *reinterpret_cast<const float4*>(B + (size_t)row * HD + cg);
            }
        }

        // ---- compute: 2 k16 steps, single fp16 pass ----
        #pragma unroll
        for (int ks = 0; ks < 2; ks++) {
            const int k0 = ks * 16;
            uint32_t bh[2][4];
            #pragma unroll
            for (int bt = 0; bt < 2; bt++) {
                const uint32_t off =
                    ((uint32_t)(n_base + bt * 16 + b_row) * PITCH
                     + (uint32_t)(k0 + b_col)) * 2u;
                ldmx4(bh[bt], uB + off);
            }
            #pragma unroll
            for (int mt = 0; mt < 4; mt++) {
                uint32_t ah[4];
                const uint32_t off =
                    ((uint32_t)(m_base + mt * 16 + a_row) * PITCH
                     + (uint32_t)(k0 + a_col)) * 2u;
                ldmx4(ah, uA + off);
                #pragma unroll
                for (int nt = 0; nt < 4; nt++)
                    mma_f16(c[mt][nt], ah,
                            bh[nt >> 1][(nt & 1) * 2], bh[nt >> 1][(nt & 1) * 2 + 1]);
            }
        }
    }

    // ---- epilogue: direct STG.64, full 32B sectors (unchanged, validated) ----
    const int er = lane >> 2;
    const int ec = (lane & 3) * 2;
    #pragma unroll
    for (int mt = 0; mt < 4; mt++) {
        #pragma unroll
        for (int nt = 0; nt < 4; nt++) {
            const int row = m_base + mt * 16 + er;
            const int col = n_base + nt * 8 + ec;
            *reinterpret_cast<float2*>(C + (size_t)row * KVT + col) =
                make_float2(c[mt][nt][0], c[mt][nt][1]);
            *reinterpret_cast<float2*>(C + (size_t)(row + 8) * KVT + col) =
                make_float2(c[mt][nt][2], c[mt][nt][3]);
        }
    }
}

extern "C" void kernel_launch(void* const* d_in, const int* in_sizes, int n_in,
                              void* d_out, int out_size) {
    const float* q = (const float*)d_in[0];   // [2,16,1024,128]
    const float* k = (const float*)d_in[1];   // [2,16,4096,128]
    float* out = (float*)d_out;               // [2,16,1024,4096]
    qk_f16_kernel<<<8192, 256>>>(q, k, out);
}